// round 7
// baseline (speedup 1.0000x reference)
#include <cuda_runtime.h>
#include <cuda_fp16.h>

#define BB 256
#define SS 512
#define FF 64
#define HH 128
#define NT 256

// g_wk[gate][kp][j] = half2(W[FF+2kp][j], W[FF+2kp+1][j]) ; gates 0..3 = i,f,o,g
__device__ __align__(16) __half2 g_wk[4 * 64 * 128];
__device__ __align__(16) float2  g_xw2[2 * 64 * 128];   // [p][k][j] = (wA, wB) of gate pair p
__device__ __align__(16) float4  g_bias4[128];

__global__ void pack_kernel(const float* __restrict__ Wi, const float* __restrict__ bi,
                            const float* __restrict__ Wf, const float* __restrict__ bf,
                            const float* __restrict__ Wo, const float* __restrict__ bo,
                            const float* __restrict__ Wg, const float* __restrict__ bg) {
    const int kp = blockIdx.x;     // 0..63
    const int j  = threadIdx.x;    // 0..127
    const int d0 = FF + 2 * kp, d1 = d0 + 1;
    g_wk[0 * 8192 + kp * 128 + j] = __floats2half2_rn(Wi[d0 * HH + j], Wi[d1 * HH + j]);
    g_wk[1 * 8192 + kp * 128 + j] = __floats2half2_rn(Wf[d0 * HH + j], Wf[d1 * HH + j]);
    g_wk[2 * 8192 + kp * 128 + j] = __floats2half2_rn(Wo[d0 * HH + j], Wo[d1 * HH + j]);
    g_wk[3 * 8192 + kp * 128 + j] = __floats2half2_rn(Wg[d0 * HH + j], Wg[d1 * HH + j]);
    g_xw2[0 * 8192 + kp * 128 + j] = make_float2(Wi[kp * HH + j], Wf[kp * HH + j]);
    g_xw2[1 * 8192 + kp * 128 + j] = make_float2(Wo[kp * HH + j], Wg[kp * HH + j]);
    if (kp == 0) g_bias4[j] = make_float4(bi[j], bf[j], bo[j], bg[j]);
}

__device__ __forceinline__ float fast_ex2(float a) { float r; asm("ex2.approx.f32 %0, %1;" : "=f"(r) : "f"(a)); return r; }
__device__ __forceinline__ float fast_rcp(float a) { float r; asm("rcp.approx.f32 %0, %1;" : "=f"(r) : "f"(a)); return r; }
__device__ __forceinline__ float tanh_ex(float x) { return fmaf(-2.0f, fast_rcp(1.0f + fast_ex2(2.8853900817779268f * x)), 1.0f); }

__device__ __forceinline__ __half2 u2h2(unsigned u) { __half2 r; *reinterpret_cast<unsigned*>(&r) = u; return r; }
__device__ __forceinline__ unsigned h2u(__half2 h) { return *reinterpret_cast<unsigned*>(&h); }
__device__ __forceinline__ __half2 tanh_h2(__half2 a) {
    unsigned r, x = h2u(a);
    asm("tanh.approx.f16x2 %0, %1;" : "=r"(r) : "r"(x));
    return u2h2(r);
}
__device__ __forceinline__ __half2 pairsum(__half2 a, __half2 b) {
    const unsigned lo = __byte_perm(h2u(a), h2u(b), 0x5410);
    const unsigned hi = __byte_perm(h2u(a), h2u(b), 0x7632);
    return __hadd2(u2h2(lo), u2h2(hi));
}
__device__ __forceinline__ __half2 red8(const __half2* a) {
    return __hadd2(__hadd2(__hadd2(a[0], a[1]), __hadd2(a[2], a[3])),
                   __hadd2(__hadd2(a[4], a[5]), __hadd2(a[6], a[7])));
}

// Smem: [0,131072) float2 s_xw | [131072,+1088) half s_h16[2 buf][2 b stride 136][128] | s_x
#define SMH_OFF 131072
#define SX_OFF  132160
#define SMEM_BYTES (132160 + 512)

__global__ void __launch_bounds__(NT, 1)
clstm_kernel(const float* __restrict__ x, const float* __restrict__ td, float* __restrict__ out) {
    extern __shared__ char sm[];
    float2* s_xw  = reinterpret_cast<float2*>(sm);
    __half* s_h16 = reinterpret_cast<__half*>(sm + SMH_OFF);
    float*  s_x   = reinterpret_cast<float*>(sm + SX_OFF);

    const int t    = threadIdx.x;
    const int lane = t & 31;
    const int j    = ((t >> 5) << 4) | (lane & 15);
    const int p    = (lane >> 4) & 1;        // 0: gates(i,f), owns c ; 1: gates(o,g), owns h
    const int b0   = blockIdx.x * 2;

    // Weights: own 2 gates over FULL k (64 k-pairs). 128 regs, shared across both batches.
    __half2 wA[64], wB[64];
#pragma unroll
    for (int q = 0; q < 64; q++) {
        wA[q] = g_wk[(2 * p) * 8192 + q * 128 + j];
        wB[q] = g_wk[(2 * p + 1) * 8192 + q * 128 + j];
    }
#pragma unroll 4
    for (int i = t; i < 2 * FF * 128; i += NT) s_xw[i] = g_xw2[i];
    const float4 bias4 = g_bias4[j];
    const float biasA = p ? bias4.z : bias4.x;
    const float biasB = p ? bias4.w : bias4.y;

    // activation constants: p0 -> (sigmoid, sigmoid) ; p1 -> (sigmoid(o), tanh(g))
    const __half2 SCL = p ? __floats2half2_rn(0.5f, 1.0f) : __floats2half2_rn(0.5f, 0.5f);
    const __half2 SAD = p ? __floats2half2_rn(0.5f, 0.0f) : __floats2half2_rn(0.5f, 0.5f);

    // Per-thread state for BOTH batches: S = stage state (c for p0, h for p1); B = base
    float S0 = 0.f, S1 = 0.f, B0 = 0.f, B1 = 0.f, tc0 = 0.f, tc1 = 0.f;
    int buf = 0;
    for (int i = t; i < 544; i += NT) s_h16[i] = __float2half_rn(0.f);
    __syncthreads();

#pragma unroll 1
    for (int sidx = 0; sidx < SS; sidx++) {
        if (t < 2 * FF)
            s_x[t] = x[(size_t)(b0 + (t >> 6)) * SS * FF + (size_t)sidx * FF + (t & 63)];
        const float dt0 = fminf(__ldg(&td[(size_t)b0 * SS + sidx]), 1.0f) * 0.25f;
        const float dt1 = fminf(__ldg(&td[(size_t)(b0 + 1) * SS + sidx]), 1.0f) * 0.25f;
        __syncthreads();

        // pre = bias + x_t @ W_x (fp32), own 2 gates, both batches; no shfl needed
        float pA0 = 0.f, pB0 = 0.f, pA1 = 0.f, pB1 = 0.f;
#pragma unroll 8
        for (int k = 0; k < FF; k++) {
            const float2 wv = s_xw[p * 8192 + k * 128 + j];
            const float x0 = s_x[k], x1 = s_x[64 + k];
            pA0 = fmaf(x0, wv.x, pA0); pB0 = fmaf(x0, wv.y, pB0);
            pA1 = fmaf(x1, wv.x, pA1); pB1 = fmaf(x1, wv.y, pB1);
        }
        const __half2 pre0 = __floats2half2_rn(biasA + pA0, biasB + pB0);
        const __half2 pre1 = __floats2half2_rn(biasA + pA1, biasB + pB1);

#pragma unroll 1
        for (int sub = 0; sub < 4; sub++) {
            float acc0 = 0.f, acc1 = 0.f;
#pragma unroll 1
            for (int m = 0; m < 4; m++) {
                // Early p-exchange of tanh(c) (regs from prev eval) — hides under MAC.
                const float tcx0 = __uint_as_float(__shfl_xor_sync(0xffffffffu, __float_as_uint(tc0), 16));
                const float tcx1 = __uint_as_float(__shfl_xor_sync(0xffffffffu, __float_as_uint(tc1), 16));

                // ---- MAC: 2 gates x 64 kp x 2 batches = 256 HFMA2; pure broadcast LDS ----
                const uint4* h0 = reinterpret_cast<const uint4*>(s_h16 + buf * 272);
                const uint4* h1 = reinterpret_cast<const uint4*>(s_h16 + buf * 272 + 136);
                __half2 aA0[8], aB0[8], aA1[8], aB1[8];
                uint4 c0 = h0[0], c1 = h1[0];
#pragma unroll
                for (int r = 0; r < 16; r++) {
                    const uint4 d0 = c0, d1 = c1;
                    if (r < 15) { c0 = h0[r + 1]; c1 = h1[r + 1]; }
                    const __half2 e0[4] = {u2h2(d0.x), u2h2(d0.y), u2h2(d0.z), u2h2(d0.w)};
                    const __half2 e1[4] = {u2h2(d1.x), u2h2(d1.y), u2h2(d1.z), u2h2(d1.w)};
#pragma unroll
                    for (int q = 0; q < 4; q++) {
                        const int kp = r * 4 + q;
                        const int ch = kp & 7;
                        if (r < 2) {
                            aA0[ch] = __hmul2(e0[q], wA[kp]);
                            aB0[ch] = __hmul2(e0[q], wB[kp]);
                            aA1[ch] = __hmul2(e1[q], wA[kp]);
                            aB1[ch] = __hmul2(e1[q], wB[kp]);
                        } else {
                            aA0[ch] = __hfma2(e0[q], wA[kp], aA0[ch]);
                            aB0[ch] = __hfma2(e0[q], wB[kp], aB0[ch]);
                            aA1[ch] = __hfma2(e1[q], wA[kp], aA1[ch]);
                            aB1[ch] = __hfma2(e1[q], wB[kp], aB1[ch]);
                        }
                    }
                }
                // z per batch: (zA, zB) — complete locally, no k-shfl.
                const __half2 z0 = __hadd2(pairsum(red8(aA0), red8(aB0)), pre0);
                const __half2 z1 = __hadd2(pairsum(red8(aA1), red8(aB1)), pre1);

                // activations: 1 f16x2 MUFU per batch
                const __half2 act0 = __hfma2(tanh_h2(__hmul2(z0, SCL)), SCL, SAD);
                const __half2 act1 = __hfma2(tanh_h2(__hmul2(z1, SCL)), SCL, SAD);

                // p1 sends g (hi halves) to p0; single on-chain shfl
                const __half2 g2 = __halves2half2(__high2half(act0), __high2half(act1));
                const __half2 gr = u2h2(__shfl_xor_sync(0xffffffffu, h2u(g2), 16));

                const float lo0 = __half2float(__low2half(act0));   // i | o
                const float hi0 = __half2float(__high2half(act0));  // f | g
                const float lo1 = __half2float(__low2half(act1));
                const float hi1 = __half2float(__high2half(act1));
                const float ig0 = lo0 * __half2float(__low2half(gr));   // i*g (p0)
                const float ig1 = lo1 * __half2float(__high2half(gr));

                // unified derivative: p0: dc = f*c + (i*g - c) ; p1: dh = o*tc + (0 - h)
                const float k0 = fmaf(p ? lo0 : hi0, p ? tcx0 : S0, (p ? 0.f : ig0) - S0);
                const float k1 = fmaf(p ? lo1 : hi1, p ? tcx1 : S1, (p ? 0.f : ig1) - S1);

                const float wm = (m == 1 || m == 2) ? 2.0f : 1.0f;
                acc0 = fmaf(wm, k0, acc0);
                acc1 = fmaf(wm, k1, acc1);
                if (m < 3) {
                    const float f0 = (m < 2) ? 0.5f * dt0 : dt0;
                    const float f1 = (m < 2) ? 0.5f * dt1 : dt1;
                    S0 = fmaf(f0, k0, B0);
                    S1 = fmaf(f1, k1, B1);
                } else {
                    B0 = fmaf(dt0 * (1.0f / 6.0f), acc0, B0);
                    B1 = fmaf(dt1 * (1.0f / 6.0f), acc1, B1);
                    S0 = B0; S1 = B1;
                }
                if (p) {   // publish h for both batches
                    s_h16[(buf ^ 1) * 272 + j]       = __float2half_rn(S0);
                    s_h16[(buf ^ 1) * 272 + 136 + j] = __float2half_rn(S1);
                }
                buf ^= 1;
                __syncthreads();
                // post-barrier: tanh(c) for next eval (p0's values meaningful) — hides under next MAC
                tc0 = tanh_ex(S0);
                tc1 = tanh_ex(S1);
            }
        }
        if (p) {
            out[(size_t)b0 * SS * HH + (size_t)sidx * HH + j]       = B0;
            out[(size_t)(b0 + 1) * SS * HH + (size_t)sidx * HH + j] = B1;
        }
    }
}

extern "C" void kernel_launch(void* const* d_in, const int* in_sizes, int n_in,
                              void* d_out, int out_size) {
    const float* x  = (const float*)d_in[0];
    const float* td = (const float*)d_in[1];
    const float* Wi = (const float*)d_in[2];
    const float* bi = (const float*)d_in[3];
    const float* Wf = (const float*)d_in[4];
    const float* bf = (const float*)d_in[5];
    const float* Wo = (const float*)d_in[6];
    const float* bo = (const float*)d_in[7];
    const float* Wg = (const float*)d_in[8];
    const float* bg = (const float*)d_in[9];
    float* out = (float*)d_out;

    cudaFuncSetAttribute(clstm_kernel, cudaFuncAttributeMaxDynamicSharedMemorySize, SMEM_BYTES);

    pack_kernel<<<64, 128>>>(Wi, bi, Wf, bf, Wo, bo, Wg, bg);
    clstm_kernel<<<BB / 2, NT, SMEM_BYTES>>>(x, td, out);
}

// round 8
// speedup vs baseline: 1.0642x; 1.0642x over previous
#include <cuda_runtime.h>
#include <cuda_fp16.h>

#define BB 256
#define SS 512
#define FF 64
#define HH 128
#define NT 256

// Weights packed along k: g_wk[gate][kp][j] = half2(W[FF+2kp][j], W[FF+2kp+1][j])
__device__ __align__(16) __half2 g_wk[4 * 64 * 128];
__device__ __align__(16) float4  g_xw4[64 * 128];    // (xk,j) -> (wi,wf,wo,wg)
__device__ __align__(16) float4  g_bias4[128];

__global__ void pack_kernel(const float* __restrict__ Wi, const float* __restrict__ bi,
                            const float* __restrict__ Wf, const float* __restrict__ bf,
                            const float* __restrict__ Wo, const float* __restrict__ bo,
                            const float* __restrict__ Wg, const float* __restrict__ bg) {
    const int kp = blockIdx.x;       // 0..63 (k-pair)
    const int t  = threadIdx.x;
    const int j  = t & 127;
    const int pr = t >> 7;
    const int d0 = FF + 2 * kp, d1 = FF + 2 * kp + 1;
    if (pr == 0) {
        g_wk[0 * 8192 + kp * 128 + j] = __floats2half2_rn(Wi[d0 * HH + j], Wi[d1 * HH + j]);
        g_wk[1 * 8192 + kp * 128 + j] = __floats2half2_rn(Wf[d0 * HH + j], Wf[d1 * HH + j]);
        g_xw4[kp * 128 + j] = make_float4(Wi[kp * HH + j], Wf[kp * HH + j],
                                          Wo[kp * HH + j], Wg[kp * HH + j]);
    } else {
        g_wk[2 * 8192 + kp * 128 + j] = __floats2half2_rn(Wo[d0 * HH + j], Wo[d1 * HH + j]);
        g_wk[3 * 8192 + kp * 128 + j] = __floats2half2_rn(Wg[d0 * HH + j], Wg[d1 * HH + j]);
        if (kp == 0) g_bias4[j] = make_float4(bi[j], bf[j], bo[j], bg[j]);
    }
}

__device__ __forceinline__ float fast_ex2(float a) { float r; asm("ex2.approx.f32 %0, %1;" : "=f"(r) : "f"(a)); return r; }
__device__ __forceinline__ float fast_rcp(float a) { float r; asm("rcp.approx.f32 %0, %1;" : "=f"(r) : "f"(a)); return r; }
__device__ __forceinline__ float tanh_ex(float x) { return fmaf(-2.0f, fast_rcp(1.0f + fast_ex2(2.8853900817779268f * x)), 1.0f); }

__device__ __forceinline__ __half2 u2h2(unsigned u) { __half2 r; *reinterpret_cast<unsigned*>(&r) = u; return r; }
__device__ __forceinline__ unsigned h2u(__half2 h) { return *reinterpret_cast<unsigned*>(&h); }
__device__ __forceinline__ __half2 tanh_h2(__half2 a) {
    unsigned r, x = h2u(a);
    asm("tanh.approx.f16x2 %0, %1;" : "=r"(r) : "r"(x));
    return u2h2(r);
}
__device__ __forceinline__ __half2 pairsum(__half2 a, __half2 b) {
    const unsigned lo = __byte_perm(h2u(a), h2u(b), 0x5410);
    const unsigned hi = __byte_perm(h2u(a), h2u(b), 0x7632);
    return __hadd2(u2h2(lo), u2h2(hi));
}
__device__ __forceinline__ __half2 red4(const __half2* a) {
    return __hadd2(__hadd2(a[0], a[1]), __hadd2(a[2], a[3]));
}

// Smem: [0,131072) float4 s_xw | [131072,+1088) half s_h16[2 buf][2 b stride 136] | s_x
#define SMH_OFF 131072
#define SX_OFF  132160
#define SMEM_BYTES (132160 + 512)

__global__ void __launch_bounds__(NT, 1)
clstm_kernel(const float* __restrict__ x, const float* __restrict__ td, float* __restrict__ out) {
    extern __shared__ char sm[];
    float4* s_xw  = reinterpret_cast<float4*>(sm);
    __half* s_h16 = reinterpret_cast<__half*>(sm + SMH_OFF);
    float*  s_x   = reinterpret_cast<float*>(sm + SX_OFF);

    const int t    = threadIdx.x;
    const int lane = t & 31;
    const int j    = ((t >> 5) << 4) | (lane & 15);
    const int ks   = (lane >> 4) & 1;          // k-half AND batch owner
    const int b0   = blockIdx.x * 2;
    const int batch = b0 + ks;

    // Weights: 4 gates x 32 k-pairs (own k-half). 128 regs, shared across both batches.
    __half2 wi[32], wf[32], wo[32], wg[32];
#pragma unroll
    for (int q = 0; q < 32; q++) {
        const int kp = ks * 32 + q;
        wi[q] = g_wk[0 * 8192 + kp * 128 + j];
        wf[q] = g_wk[1 * 8192 + kp * 128 + j];
        wo[q] = g_wk[2 * 8192 + kp * 128 + j];
        wg[q] = g_wk[3 * 8192 + kp * 128 + j];
    }
#pragma unroll 4
    for (int i = t; i < FF * 128; i += NT) s_xw[i] = g_xw4[i];
    const float4 bias4 = g_bias4[j];
    const float biasA[4] = {bias4.x, bias4.y, bias4.z, bias4.w};

    const __half2 H_HALF = __floats2half2_rn(0.5f, 0.5f);
    const __half2 H_SM   = __floats2half2_rn(0.5f, 1.0f);
    const __half2 H_SB   = __floats2half2_rn(0.5f, 0.0f);

    float hB = 0.f, cB = 0.f, hS = 0.f, cS = 0.f, tcs = 0.f;
    int buf = 0;
    s_h16[t] = __float2half_rn(0.f);
    if (t < 16) s_h16[256 + t] = __float2half_rn(0.f);
    __syncthreads();

#pragma unroll 1
    for (int sidx = 0; sidx < SS; sidx++) {
        if (t < 2 * FF)
            s_x[t] = x[(size_t)(b0 + (t >> 6)) * SS * FF + (size_t)sidx * FF + (t & 63)];
        const float dt  = fminf(__ldg(&td[(size_t)batch * SS + sidx]), 1.0f) * 0.25f;
        const float dth = 0.5f * dt, dt6 = dt * (1.0f / 6.0f);
        __syncthreads();

        // pre = bias + x_t @ W_x (fp32, hoisted over all 16 evals)
        float xpa[4] = {0.f, 0.f, 0.f, 0.f}, xpb[4] = {0.f, 0.f, 0.f, 0.f};
#pragma unroll 8
        for (int q = 0; q < 32; q++) {
            const int kk = ks * 32 + q;
            const float4 wv = s_xw[kk * 128 + j];
            const float x0 = s_x[kk], x1 = s_x[64 + kk];
            xpa[0] = fmaf(x0, wv.x, xpa[0]); xpa[1] = fmaf(x0, wv.y, xpa[1]);
            xpa[2] = fmaf(x0, wv.z, xpa[2]); xpa[3] = fmaf(x0, wv.w, xpa[3]);
            xpb[0] = fmaf(x1, wv.x, xpb[0]); xpb[1] = fmaf(x1, wv.y, xpb[1]);
            xpb[2] = fmaf(x1, wv.z, xpb[2]); xpb[3] = fmaf(x1, wv.w, xpb[3]);
        }
        float pre[4];
#pragma unroll
        for (int g = 0; g < 4; g++) {
            const float mine = ks ? xpb[g] : xpa[g];
            const float oth  = ks ? xpa[g] : xpb[g];
            pre[g] = biasA[g] + mine + __shfl_xor_sync(0xffffffffu, oth, 16);
        }
        const __half2 pre_if = __floats2half2_rn(pre[0], pre[1]);
        const __half2 pre_og = __floats2half2_rn(pre[2], pre[3]);

#pragma unroll 1
        for (int sub = 0; sub < 4; sub++) {
            float accH = 0.f, accC = 0.f;
#pragma unroll 1
            for (int m = 0; m < 4; m++) {
                const __half* hb = s_h16 + buf * 272;
                const uint4* hpo = reinterpret_cast<const uint4*>(hb) + 25 * ks;        // own batch
                const uint4* hpx = reinterpret_cast<const uint4*>(hb) + (17 - 9 * ks);  // other batch

                // ---- MAC: 256 HFMA2, 16 LDS.128 (broadcast), prefetch distance 2 ----
                uint4 ho[8], hx[8];
                ho[0] = hpo[0]; hx[0] = hpx[0];
                ho[1] = hpo[1]; hx[1] = hpx[1];
                __half2 aOi[4], aOf[4], aOo[4], aOg[4];
                __half2 aXi[4], aXf[4], aXo[4], aXg[4];
#pragma unroll
                for (int r = 0; r < 8; r++) {
                    if (r < 6) { ho[r + 2] = hpo[r + 2]; hx[r + 2] = hpx[r + 2]; }
                    const uint4 co = ho[r], cx = hx[r];
                    const __half2 e0[4] = {u2h2(co.x), u2h2(co.y), u2h2(co.z), u2h2(co.w)};
                    const __half2 e1[4] = {u2h2(cx.x), u2h2(cx.y), u2h2(cx.z), u2h2(cx.w)};
#pragma unroll
                    for (int q = 0; q < 4; q++) {
                        const int kp = r * 4 + q;
                        if (r == 0) {
                            aOi[q] = __hmul2(e0[q], wi[kp]);
                            aOf[q] = __hmul2(e0[q], wf[kp]);
                            aOo[q] = __hmul2(e0[q], wo[kp]);
                            aOg[q] = __hmul2(e0[q], wg[kp]);
                            aXi[q] = __hmul2(e1[q], wi[kp]);
                            aXf[q] = __hmul2(e1[q], wf[kp]);
                            aXo[q] = __hmul2(e1[q], wo[kp]);
                            aXg[q] = __hmul2(e1[q], wg[kp]);
                        } else {
                            aOi[q] = __hfma2(e0[q], wi[kp], aOi[q]);
                            aOf[q] = __hfma2(e0[q], wf[kp], aOf[q]);
                            aOo[q] = __hfma2(e0[q], wo[kp], aOo[q]);
                            aOg[q] = __hfma2(e0[q], wg[kp], aOg[q]);
                            aXi[q] = __hfma2(e1[q], wi[kp], aXi[q]);
                            aXf[q] = __hfma2(e1[q], wf[kp], aXf[q]);
                            aXo[q] = __hfma2(e1[q], wo[kp], aXo[q]);
                            aXg[q] = __hfma2(e1[q], wg[kp], aXg[q]);
                        }
                    }
                }
                // reduce: per gate chains -> half2, then pair-transpose to (Sum_A, Sum_B)
                const __half2 tif_o = pairsum(red4(aOi), red4(aOf));
                const __half2 tog_o = pairsum(red4(aOo), red4(aOg));
                const __half2 tif_x = pairsum(red4(aXi), red4(aXf));
                const __half2 tog_x = pairsum(red4(aXo), red4(aXg));

                const unsigned e_if = __shfl_xor_sync(0xffffffffu, h2u(tif_x), 16);
                const unsigned e_og = __shfl_xor_sync(0xffffffffu, h2u(tog_x), 16);

                const __half2 z_if = __hadd2(__hadd2(pre_if, tif_o), u2h2(e_if));
                const __half2 z_og = __hadd2(__hadd2(pre_og, tog_o), u2h2(e_og));

                // (i,f): one f16x2 MUFU; (o,g): one f16x2 MUFU (o sigmoid, g tanh)
                const __half2 s_if = __hfma2(tanh_h2(__hmul2(z_if, H_HALF)), H_HALF, H_HALF);
                const __half2 s_og = __hfma2(tanh_h2(__hmul2(z_og, H_SM)), H_SM, H_SB);

                const __half2 g2 = __high2half2(s_og);            // (g, g)
                const __half2 m2 = __hmul2(s_if, g2);             // (i*g, f*g)
                const float ig = __half2float(__low2half(m2));
                const float sf = __half2float(__high2half(s_if));
                const float so = __half2float(__low2half(s_og));

                const float kH = fmaf(so, tcs, -hS);              // dh = o*tanh(c) - h
                const float kC = fmaf(sf, cS, ig - cS);           // dc = i*g + (f-1)*c
                const float wm = (m == 1 || m == 2) ? 2.0f : 1.0f;
                accH = fmaf(wm, kH, accH);
                accC = fmaf(wm, kC, accC);
                if (m < 3) {
                    const float bd = (m < 2) ? dth : dt;
                    hS = fmaf(bd, kH, hB);
                    cS = fmaf(bd, kC, cB);
                } else {
                    hB = fmaf(dt6, accH, hB);
                    cB = fmaf(dt6, accC, cB);
                    hS = hB; cS = cB;
                }
                s_h16[(buf ^ 1) * 272 + ks * 136 + j] = __float2half_rn(hS);
                buf ^= 1;
                __syncthreads();
                // post-barrier: tanh(c) for next eval hides under the next MAC issue
                tcs = tanh_ex(cS);
            }
        }
        out[(size_t)batch * SS * HH + (size_t)sidx * HH + j] = hB;
    }
}

extern "C" void kernel_launch(void* const* d_in, const int* in_sizes, int n_in,
                              void* d_out, int out_size) {
    const float* x  = (const float*)d_in[0];
    const float* td = (const float*)d_in[1];
    const float* Wi = (const float*)d_in[2];
    const float* bi = (const float*)d_in[3];
    const float* Wf = (const float*)d_in[4];
    const float* bf = (const float*)d_in[5];
    const float* Wo = (const float*)d_in[6];
    const float* bo = (const float*)d_in[7];
    const float* Wg = (const float*)d_in[8];
    const float* bg = (const float*)d_in[9];
    float* out = (float*)d_out;

    cudaFuncSetAttribute(clstm_kernel, cudaFuncAttributeMaxDynamicSharedMemorySize, SMEM_BYTES);

    pack_kernel<<<64, NT>>>(Wi, bi, Wf, bf, Wo, bo, Wg, bg);
    clstm_kernel<<<BB / 2, NT, SMEM_BYTES>>>(x, td, out);
}

// round 9
// speedup vs baseline: 1.0781x; 1.0131x over previous
#include <cuda_runtime.h>
#include <cuda_fp16.h>

#define BB 256
#define SS 512
#define FF 64
#define HH 128
#define NT 256

// Weights packed along k: g_wk[gate][kp][j] = half2(W[FF+2kp][j], W[FF+2kp+1][j])
__device__ __align__(16) __half2 g_wk[4 * 64 * 128];
__device__ __align__(16) float4  g_xw4[64 * 128];    // (xk,j) -> (wi,wf,wo,wg)
__device__ __align__(16) float4  g_bias4[128];

__global__ void pack_kernel(const float* __restrict__ Wi, const float* __restrict__ bi,
                            const float* __restrict__ Wf, const float* __restrict__ bf,
                            const float* __restrict__ Wo, const float* __restrict__ bo,
                            const float* __restrict__ Wg, const float* __restrict__ bg) {
    const int kp = blockIdx.x;       // 0..63 (k-pair)
    const int t  = threadIdx.x;
    const int j  = t & 127;
    const int pr = t >> 7;
    const int d0 = FF + 2 * kp, d1 = FF + 2 * kp + 1;
    if (pr == 0) {
        g_wk[0 * 8192 + kp * 128 + j] = __floats2half2_rn(Wi[d0 * HH + j], Wi[d1 * HH + j]);
        g_wk[1 * 8192 + kp * 128 + j] = __floats2half2_rn(Wf[d0 * HH + j], Wf[d1 * HH + j]);
        g_xw4[kp * 128 + j] = make_float4(Wi[kp * HH + j], Wf[kp * HH + j],
                                          Wo[kp * HH + j], Wg[kp * HH + j]);
    } else {
        g_wk[2 * 8192 + kp * 128 + j] = __floats2half2_rn(Wo[d0 * HH + j], Wo[d1 * HH + j]);
        g_wk[3 * 8192 + kp * 128 + j] = __floats2half2_rn(Wg[d0 * HH + j], Wg[d1 * HH + j]);
        if (kp == 0) g_bias4[j] = make_float4(bi[j], bf[j], bo[j], bg[j]);
    }
}

__device__ __forceinline__ float fast_ex2(float a) { float r; asm("ex2.approx.f32 %0, %1;" : "=f"(r) : "f"(a)); return r; }
__device__ __forceinline__ float fast_rcp(float a) { float r; asm("rcp.approx.f32 %0, %1;" : "=f"(r) : "f"(a)); return r; }
__device__ __forceinline__ float tanh_ex(float x) { return fmaf(-2.0f, fast_rcp(1.0f + fast_ex2(2.8853900817779268f * x)), 1.0f); }

__device__ __forceinline__ __half2 u2h2(unsigned u) { __half2 r; *reinterpret_cast<unsigned*>(&r) = u; return r; }
__device__ __forceinline__ unsigned h2u(__half2 h) { return *reinterpret_cast<unsigned*>(&h); }
__device__ __forceinline__ __half2 tanh_h2(__half2 a) {
    unsigned r, x = h2u(a);
    asm("tanh.approx.f16x2 %0, %1;" : "=r"(r) : "r"(x));
    return u2h2(r);
}
__device__ __forceinline__ __half2 pairsum(__half2 a, __half2 b) {
    const unsigned lo = __byte_perm(h2u(a), h2u(b), 0x5410);
    const unsigned hi = __byte_perm(h2u(a), h2u(b), 0x7632);
    return __hadd2(u2h2(lo), u2h2(hi));
}
__device__ __forceinline__ __half2 red4(const __half2* a) {
    return __hadd2(__hadd2(a[0], a[1]), __hadd2(a[2], a[3]));
}

// Smem: [0,131072) float4 s_xw | [131072,+1088) half s_h16[2 buf] | [132160,+1024) float s_x[2][128]
#define SMH_OFF 131072
#define SX_OFF  132160
#define SMEM_BYTES (132160 + 1024)

__global__ void __launch_bounds__(NT, 1)
clstm_kernel(const float* __restrict__ x, const float* __restrict__ td, float* __restrict__ out) {
    extern __shared__ char sm[];
    float4* s_xw  = reinterpret_cast<float4*>(sm);
    __half* s_h16 = reinterpret_cast<__half*>(sm + SMH_OFF);
    float*  s_x   = reinterpret_cast<float*>(sm + SX_OFF);   // [2][128]

    const int t    = threadIdx.x;
    const int lane = t & 31;
    const int j    = ((t >> 5) << 4) | (lane & 15);
    const int ks   = (lane >> 4) & 1;          // k-half AND batch owner
    const int b0   = blockIdx.x * 2;
    const int batch = b0 + ks;

    // Weights: 4 gates x 32 k-pairs (own k-half). 128 regs, shared across both batches.
    __half2 wi[32], wf[32], wo[32], wg[32];
#pragma unroll
    for (int q = 0; q < 32; q++) {
        const int kp = ks * 32 + q;
        wi[q] = g_wk[0 * 8192 + kp * 128 + j];
        wf[q] = g_wk[1 * 8192 + kp * 128 + j];
        wo[q] = g_wk[2 * 8192 + kp * 128 + j];
        wg[q] = g_wk[3 * 8192 + kp * 128 + j];
    }
#pragma unroll 4
    for (int i = t; i < FF * 128; i += NT) s_xw[i] = g_xw4[i];
    const float4 bias4 = g_bias4[j];
    const float biasA[4] = {bias4.x, bias4.y, bias4.z, bias4.w};

    const __half2 H_HALF = __floats2half2_rn(0.5f, 0.5f);
    const __half2 H_SM   = __floats2half2_rn(0.5f, 1.0f);
    const __half2 H_SB   = __floats2half2_rn(0.5f, 0.0f);

    float hB = 0.f, cB = 0.f, hS = 0.f, cS = 0.f, tcs = 0.f;
    int buf = 0;
    s_h16[t] = __float2half_rn(0.f);
    if (t < 16) s_h16[256 + t] = __float2half_rn(0.f);

    // prologue prefetch: x[0] into s_x[0], dt for sidx 0 into regs
    if (t < 2 * FF)
        s_x[t] = x[(size_t)(b0 + (t >> 6)) * SS * FF + (t & 63)];
    float dtc = fminf(__ldg(&td[(size_t)batch * SS]), 1.0f) * 0.25f;
    __syncthreads();

#pragma unroll 1
    for (int sidx = 0; sidx < SS; sidx++) {
        const int xb = sidx & 1;
        const float dt  = dtc;
        const float dth = 0.5f * dt, dt6 = dt * (1.0f / 6.0f);

        // prefetch next timestep's x / dt (consumed next iteration; hidden by 16 evals)
        const int nidx = (sidx + 1 < SS) ? sidx + 1 : sidx;
        float xr = 0.f;
        if (t < 2 * FF)
            xr = x[(size_t)(b0 + (t >> 6)) * SS * FF + (size_t)nidx * FF + (t & 63)];
        const float dtn = fminf(__ldg(&td[(size_t)batch * SS + nidx]), 1.0f) * 0.25f;

        // pre = bias + x_t @ W_x (fp32, hoisted over all 16 evals)
        float xpa[4] = {0.f, 0.f, 0.f, 0.f}, xpb[4] = {0.f, 0.f, 0.f, 0.f};
#pragma unroll 8
        for (int q = 0; q < 32; q++) {
            const int kk = ks * 32 + q;
            const float4 wv = s_xw[kk * 128 + j];
            const float x0 = s_x[xb * 128 + kk], x1 = s_x[xb * 128 + 64 + kk];
            xpa[0] = fmaf(x0, wv.x, xpa[0]); xpa[1] = fmaf(x0, wv.y, xpa[1]);
            xpa[2] = fmaf(x0, wv.z, xpa[2]); xpa[3] = fmaf(x0, wv.w, xpa[3]);
            xpb[0] = fmaf(x1, wv.x, xpb[0]); xpb[1] = fmaf(x1, wv.y, xpb[1]);
            xpb[2] = fmaf(x1, wv.z, xpb[2]); xpb[3] = fmaf(x1, wv.w, xpb[3]);
        }
        float pre[4];
#pragma unroll
        for (int g = 0; g < 4; g++) {
            const float mine = ks ? xpb[g] : xpa[g];
            const float oth  = ks ? xpa[g] : xpb[g];
            pre[g] = biasA[g] + mine + __shfl_xor_sync(0xffffffffu, oth, 16);
        }
        const __half2 pre_if = __floats2half2_rn(pre[0], pre[1]);
        const __half2 pre_og = __floats2half2_rn(pre[2], pre[3]);

#pragma unroll 1
        for (int sub = 0; sub < 4; sub++) {
            float accH = 0.f, accC = 0.f;
#pragma unroll 1
            for (int m = 0; m < 4; m++) {
                const __half* hb = s_h16 + buf * 272;
                const uint4* hpo = reinterpret_cast<const uint4*>(hb) + 25 * ks;        // own batch
                const uint4* hpx = reinterpret_cast<const uint4*>(hb) + (17 - 9 * ks);  // other batch

                // ---- MAC: 256 HFMA2, 16 LDS.128 (broadcast), prefetch distance 2 ----
                uint4 ho[8], hx[8];
                ho[0] = hpo[0]; hx[0] = hpx[0];
                ho[1] = hpo[1]; hx[1] = hpx[1];
                __half2 aOi[4], aOf[4], aOo[4], aOg[4];
                __half2 aXi[4], aXf[4], aXo[4], aXg[4];
#pragma unroll
                for (int r = 0; r < 8; r++) {
                    if (r < 6) { ho[r + 2] = hpo[r + 2]; hx[r + 2] = hpx[r + 2]; }
                    const uint4 co = ho[r], cx = hx[r];
                    const __half2 e0[4] = {u2h2(co.x), u2h2(co.y), u2h2(co.z), u2h2(co.w)};
                    const __half2 e1[4] = {u2h2(cx.x), u2h2(cx.y), u2h2(cx.z), u2h2(cx.w)};
#pragma unroll
                    for (int q = 0; q < 4; q++) {
                        const int kp = r * 4 + q;
                        if (r == 0) {
                            aOi[q] = __hmul2(e0[q], wi[kp]);
                            aOf[q] = __hmul2(e0[q], wf[kp]);
                            aOo[q] = __hmul2(e0[q], wo[kp]);
                            aOg[q] = __hmul2(e0[q], wg[kp]);
                            aXi[q] = __hmul2(e1[q], wi[kp]);
                            aXf[q] = __hmul2(e1[q], wf[kp]);
                            aXo[q] = __hmul2(e1[q], wo[kp]);
                            aXg[q] = __hmul2(e1[q], wg[kp]);
                        } else {
                            aOi[q] = __hfma2(e0[q], wi[kp], aOi[q]);
                            aOf[q] = __hfma2(e0[q], wf[kp], aOf[q]);
                            aOo[q] = __hfma2(e0[q], wo[kp], aOo[q]);
                            aOg[q] = __hfma2(e0[q], wg[kp], aOg[q]);
                            aXi[q] = __hfma2(e1[q], wi[kp], aXi[q]);
                            aXf[q] = __hfma2(e1[q], wf[kp], aXf[q]);
                            aXo[q] = __hfma2(e1[q], wo[kp], aXo[q]);
                            aXg[q] = __hfma2(e1[q], wg[kp], aXg[q]);
                        }
                    }
                }
                // (o,g) path FIRST — h-publish chain is barrier-critical
                const __half2 tog_x = pairsum(red4(aXo), red4(aXg));
                const unsigned e_og = __shfl_xor_sync(0xffffffffu, h2u(tog_x), 16);
                const __half2 tog_o = pairsum(red4(aOo), red4(aOg));
                const __half2 z_og  = __hadd2(__hadd2(pre_og, tog_o), u2h2(e_og));
                const __half2 s_og  = __hfma2(tanh_h2(__hmul2(z_og, H_SM)), H_SM, H_SB);

                const float so = __half2float(__low2half(s_og));
                const float kH = fmaf(so, tcs, -hS);              // dh = o*tanh(c) - h
                const float wm = (m == 1 || m == 2) ? 2.0f : 1.0f;
                accH = fmaf(wm, kH, accH);
                if (m < 3) {
                    hS = fmaf((m < 2) ? dth : dt, kH, hB);
                } else {
                    hB = fmaf(dt6, accH, hB);
                    hS = hB;
                }
                s_h16[(buf ^ 1) * 272 + ks * 136 + j] = __float2half_rn(hS);   // earliest publish

                // (i,f) path — off the barrier-critical chain
                const __half2 tif_x = pairsum(red4(aXi), red4(aXf));
                const unsigned e_if = __shfl_xor_sync(0xffffffffu, h2u(tif_x), 16);
                const __half2 tif_o = pairsum(red4(aOi), red4(aOf));
                const __half2 z_if  = __hadd2(__hadd2(pre_if, tif_o), u2h2(e_if));
                const __half2 s_if  = __hfma2(tanh_h2(__hmul2(z_if, H_HALF)), H_HALF, H_HALF);

                const __half2 g2 = __high2half2(s_og);            // (g, g)
                const __half2 m2 = __hmul2(s_if, g2);             // (i*g, f*g)
                const float ig = __half2float(__low2half(m2));
                const float sf = __half2float(__high2half(s_if));

                const float kC = fmaf(sf, cS, ig - cS);           // dc = i*g + (f-1)*c
                accC = fmaf(wm, kC, accC);
                if (m < 3) {
                    cS = fmaf((m < 2) ? dth : dt, kC, cB);
                } else {
                    cB = fmaf(dt6, accC, cB);
                    cS = cB;
                }

                // last eval of the timestep also publishes next x (rides the same barrier)
                if (sub == 3 && m == 3 && t < 2 * FF)
                    s_x[(xb ^ 1) * 128 + t] = xr;

                buf ^= 1;
                __syncthreads();
                // post-barrier: tanh(c) for next eval hides under the next MAC issue
                tcs = tanh_ex(cS);
            }
        }
        dtc = dtn;
        out[(size_t)batch * SS * HH + (size_t)sidx * HH + j] = hB;
    }
}

extern "C" void kernel_launch(void* const* d_in, const int* in_sizes, int n_in,
                              void* d_out, int out_size) {
    const float* x  = (const float*)d_in[0];
    const float* td = (const float*)d_in[1];
    const float* Wi = (const float*)d_in[2];
    const float* bi = (const float*)d_in[3];
    const float* Wf = (const float*)d_in[4];
    const float* bf = (const float*)d_in[5];
    const float* Wo = (const float*)d_in[6];
    const float* bo = (const float*)d_in[7];
    const float* Wg = (const float*)d_in[8];
    const float* bg = (const float*)d_in[9];
    float* out = (float*)d_out;

    cudaFuncSetAttribute(clstm_kernel, cudaFuncAttributeMaxDynamicSharedMemorySize, SMEM_BYTES);

    pack_kernel<<<64, NT>>>(Wi, bi, Wf, bf, Wo, bo, Wg, bg);
    clstm_kernel<<<BB / 2, NT, SMEM_BYTES>>>(x, td, out);
}

// round 10
// speedup vs baseline: 1.2008x; 1.1138x over previous
#include <cuda_runtime.h>
#include <cuda_fp16.h>

#define BB 256
#define SS 512
#define FF 64
#define HH 128
#define NT 256

// Weights packed along k: g_wk[gate][kp][j] = half2(W[FF+2kp][j], W[FF+2kp+1][j])
// Gates i,f,o are PRE-SCALED by 0.5 (exact) so sigmoid args need no runtime mul.
__device__ __align__(16) __half2 g_wk[4 * 64 * 128];
__device__ __align__(16) float4  g_xw4[64 * 128];    // (xk,j) -> (.5wi,.5wf,.5wo,wg)
__device__ __align__(16) float4  g_bias4[128];

__global__ void pack_kernel(const float* __restrict__ Wi, const float* __restrict__ bi,
                            const float* __restrict__ Wf, const float* __restrict__ bf,
                            const float* __restrict__ Wo, const float* __restrict__ bo,
                            const float* __restrict__ Wg, const float* __restrict__ bg) {
    const int kp = blockIdx.x;       // 0..63 (k-pair)
    const int t  = threadIdx.x;
    const int j  = t & 127;
    const int pr = t >> 7;
    const int d0 = FF + 2 * kp, d1 = FF + 2 * kp + 1;
    if (pr == 0) {
        g_wk[0 * 8192 + kp * 128 + j] = __floats2half2_rn(0.5f * Wi[d0 * HH + j], 0.5f * Wi[d1 * HH + j]);
        g_wk[1 * 8192 + kp * 128 + j] = __floats2half2_rn(0.5f * Wf[d0 * HH + j], 0.5f * Wf[d1 * HH + j]);
        g_xw4[kp * 128 + j] = make_float4(0.5f * Wi[kp * HH + j], 0.5f * Wf[kp * HH + j],
                                          0.5f * Wo[kp * HH + j], Wg[kp * HH + j]);
    } else {
        g_wk[2 * 8192 + kp * 128 + j] = __floats2half2_rn(0.5f * Wo[d0 * HH + j], 0.5f * Wo[d1 * HH + j]);
        g_wk[3 * 8192 + kp * 128 + j] = __floats2half2_rn(Wg[d0 * HH + j], Wg[d1 * HH + j]);
        if (kp == 0) g_bias4[j] = make_float4(0.5f * bi[j], 0.5f * bf[j], 0.5f * bo[j], bg[j]);
    }
}

__device__ __forceinline__ float fast_ex2(float a) { float r; asm("ex2.approx.f32 %0, %1;" : "=f"(r) : "f"(a)); return r; }
__device__ __forceinline__ float fast_rcp(float a) { float r; asm("rcp.approx.f32 %0, %1;" : "=f"(r) : "f"(a)); return r; }
__device__ __forceinline__ float tanh_ex(float x) { return fmaf(-2.0f, fast_rcp(1.0f + fast_ex2(2.8853900817779268f * x)), 1.0f); }

__device__ __forceinline__ __half2 u2h2(unsigned u) { __half2 r; *reinterpret_cast<unsigned*>(&r) = u; return r; }
__device__ __forceinline__ unsigned h2u(__half2 h) { return *reinterpret_cast<unsigned*>(&h); }
__device__ __forceinline__ __half2 tanh_h2(__half2 a) {
    unsigned r, x = h2u(a);
    asm("tanh.approx.f16x2 %0, %1;" : "=r"(r) : "r"(x));
    return u2h2(r);
}
__device__ __forceinline__ __half2 pairsum(__half2 a, __half2 b) {
    const unsigned lo = __byte_perm(h2u(a), h2u(b), 0x5410);
    const unsigned hi = __byte_perm(h2u(a), h2u(b), 0x7632);
    return __hadd2(u2h2(lo), u2h2(hi));
}
__device__ __forceinline__ __half2 red4(const __half2* a) {
    return __hadd2(__hadd2(a[0], a[1]), __hadd2(a[2], a[3]));
}

// Smem: [0,131072) float4 s_xw | [131072,+1088) half s_h16[2 buf] | [132160,+1024) float s_x[2][128]
#define SMH_OFF 131072
#define SX_OFF  132160
#define SMEM_BYTES (132160 + 1024)

__global__ void __launch_bounds__(NT, 1)
clstm_kernel(const float* __restrict__ x, const float* __restrict__ td, float* __restrict__ out) {
    extern __shared__ char sm[];
    float4* s_xw  = reinterpret_cast<float4*>(sm);
    __half* s_h16 = reinterpret_cast<__half*>(sm + SMH_OFF);
    float*  s_x   = reinterpret_cast<float*>(sm + SX_OFF);   // [2][128]

    const int t    = threadIdx.x;
    const int lane = t & 31;
    const int j    = ((t >> 5) << 4) | (lane & 15);
    const int ks   = (lane >> 4) & 1;          // k-half AND batch owner
    const int b0   = blockIdx.x * 2;
    const int batch = b0 + ks;

    // Weights: 4 gates x 32 k-pairs (own k-half). 128 regs, shared across both batches.
    __half2 wi[32], wf[32], wo[32], wg[32];
#pragma unroll
    for (int q = 0; q < 32; q++) {
        const int kp = ks * 32 + q;
        wi[q] = g_wk[0 * 8192 + kp * 128 + j];
        wf[q] = g_wk[1 * 8192 + kp * 128 + j];
        wo[q] = g_wk[2 * 8192 + kp * 128 + j];
        wg[q] = g_wk[3 * 8192 + kp * 128 + j];
    }
#pragma unroll 4
    for (int i = t; i < FF * 128; i += NT) s_xw[i] = g_xw4[i];
    const float4 bias4 = g_bias4[j];
    const float biasA[4] = {bias4.x, bias4.y, bias4.z, bias4.w};

    const __half2 H_HALF = __floats2half2_rn(0.5f, 0.5f);
    const __half2 H_SM   = __floats2half2_rn(0.5f, 1.0f);
    const __half2 H_SB   = __floats2half2_rn(0.5f, 0.0f);

    float hB = 0.f, cB = 0.f, hS = 0.f, cS = 0.f, tcs = 0.f;
    int buf = 0;
    s_h16[t] = __float2half_rn(0.f);
    if (t < 16) s_h16[256 + t] = __float2half_rn(0.f);

    // prologue prefetch: x[0] into s_x[0], dt for sidx 0 into regs
    if (t < 2 * FF)
        s_x[t] = x[(size_t)(b0 + (t >> 6)) * SS * FF + (t & 63)];
    float dtc = fminf(__ldg(&td[(size_t)batch * SS]), 1.0f) * 0.25f;
    __syncthreads();

#pragma unroll 1
    for (int sidx = 0; sidx < SS; sidx++) {
        const int xb = sidx & 1;
        const float dt  = dtc;
        const float dth = 0.5f * dt, dt6 = dt * (1.0f / 6.0f);

        // prefetch next timestep's x / dt (consumed next iteration; hidden by 16 evals)
        const int nidx = (sidx + 1 < SS) ? sidx + 1 : sidx;
        float xr = 0.f;
        if (t < 2 * FF)
            xr = x[(size_t)(b0 + (t >> 6)) * SS * FF + (size_t)nidx * FF + (t & 63)];
        const float dtn = fminf(__ldg(&td[(size_t)batch * SS + nidx]), 1.0f) * 0.25f;

        // pre = bias + x_t @ W_x (fp32, hoisted over all 16 evals); gates i,f,o pre-scaled
        float xpa[4] = {0.f, 0.f, 0.f, 0.f}, xpb[4] = {0.f, 0.f, 0.f, 0.f};
#pragma unroll 8
        for (int q = 0; q < 32; q++) {
            const int kk = ks * 32 + q;
            const float4 wv = s_xw[kk * 128 + j];
            const float x0 = s_x[xb * 128 + kk], x1 = s_x[xb * 128 + 64 + kk];
            xpa[0] = fmaf(x0, wv.x, xpa[0]); xpa[1] = fmaf(x0, wv.y, xpa[1]);
            xpa[2] = fmaf(x0, wv.z, xpa[2]); xpa[3] = fmaf(x0, wv.w, xpa[3]);
            xpb[0] = fmaf(x1, wv.x, xpb[0]); xpb[1] = fmaf(x1, wv.y, xpb[1]);
            xpb[2] = fmaf(x1, wv.z, xpb[2]); xpb[3] = fmaf(x1, wv.w, xpb[3]);
        }
        float pre[4];
#pragma unroll
        for (int g = 0; g < 4; g++) {
            const float mine = ks ? xpb[g] : xpa[g];
            const float oth  = ks ? xpa[g] : xpb[g];
            pre[g] = biasA[g] + mine + __shfl_xor_sync(0xffffffffu, oth, 16);
        }
        // pre injected as chain-0 initializer of each own-batch gate stream: (pre, 0) in fp16
        const __half2 ini_i = __floats2half2_rn(pre[0], 0.f);
        const __half2 ini_f = __floats2half2_rn(pre[1], 0.f);
        const __half2 ini_o = __floats2half2_rn(pre[2], 0.f);
        const __half2 ini_g = __floats2half2_rn(pre[3], 0.f);

#pragma unroll 1
        for (int sub = 0; sub < 4; sub++) {
            float accH = 0.f, accC = 0.f;
#pragma unroll
            for (int m = 0; m < 4; m++) {
                const __half* hb = s_h16 + buf * 272;
                const uint4* hpo = reinterpret_cast<const uint4*>(hb) + 25 * ks;        // own batch
                const uint4* hpx = reinterpret_cast<const uint4*>(hb) + (17 - 9 * ks);  // other batch

                // ---- MAC: 256 HFMA2, 16 LDS.128 (broadcast), prefetch distance 2 ----
                uint4 ho[8], hx[8];
                ho[0] = hpo[0]; hx[0] = hpx[0];
                ho[1] = hpo[1]; hx[1] = hpx[1];
                __half2 aOi[4], aOf[4], aOo[4], aOg[4];
                __half2 aXi[4], aXf[4], aXo[4], aXg[4];
#pragma unroll
                for (int r = 0; r < 8; r++) {
                    if (r < 6) { ho[r + 2] = hpo[r + 2]; hx[r + 2] = hpx[r + 2]; }
                    const uint4 co = ho[r], cx = hx[r];
                    const __half2 e0[4] = {u2h2(co.x), u2h2(co.y), u2h2(co.z), u2h2(co.w)};
                    const __half2 e1[4] = {u2h2(cx.x), u2h2(cx.y), u2h2(cx.z), u2h2(cx.w)};
#pragma unroll
                    for (int q = 0; q < 4; q++) {
                        const int kp = r * 4 + q;
                        if (r == 0) {
                            if (q == 0) {   // chain 0 carries pre (free injection)
                                aOi[q] = __hfma2(e0[q], wi[kp], ini_i);
                                aOf[q] = __hfma2(e0[q], wf[kp], ini_f);
                                aOo[q] = __hfma2(e0[q], wo[kp], ini_o);
                                aOg[q] = __hfma2(e0[q], wg[kp], ini_g);
                            } else {
                                aOi[q] = __hmul2(e0[q], wi[kp]);
                                aOf[q] = __hmul2(e0[q], wf[kp]);
                                aOo[q] = __hmul2(e0[q], wo[kp]);
                                aOg[q] = __hmul2(e0[q], wg[kp]);
                            }
                            aXi[q] = __hmul2(e1[q], wi[kp]);
                            aXf[q] = __hmul2(e1[q], wf[kp]);
                            aXo[q] = __hmul2(e1[q], wo[kp]);
                            aXg[q] = __hmul2(e1[q], wg[kp]);
                        } else {
                            aOi[q] = __hfma2(e0[q], wi[kp], aOi[q]);
                            aOf[q] = __hfma2(e0[q], wf[kp], aOf[q]);
                            aOo[q] = __hfma2(e0[q], wo[kp], aOo[q]);
                            aOg[q] = __hfma2(e0[q], wg[kp], aOg[q]);
                            aXi[q] = __hfma2(e1[q], wi[kp], aXi[q]);
                            aXf[q] = __hfma2(e1[q], wf[kp], aXf[q]);
                            aXo[q] = __hfma2(e1[q], wo[kp], aXo[q]);
                            aXg[q] = __hfma2(e1[q], wg[kp], aXg[q]);
                        }
                    }
                }
                // (o,g) path FIRST — h-publish chain is barrier-critical
                const __half2 tog_x = pairsum(red4(aXo), red4(aXg));
                const unsigned e_og = __shfl_xor_sync(0xffffffffu, h2u(tog_x), 16);
                const __half2 tog_o = pairsum(red4(aOo), red4(aOg));   // includes pre
                const __half2 z_og  = __hadd2(tog_o, u2h2(e_og));
                const __half2 s_og  = __hfma2(tanh_h2(z_og), H_SM, H_SB);  // z pre-scaled

                const float so = __half2float(__low2half(s_og));
                const float kH = fmaf(so, tcs, -hS);              // dh = o*tanh(c) - h
                if (m == 0) accH = kH;
                else if (m == 3) accH += kH;
                else accH = fmaf(2.0f, kH, accH);
                if (m < 3) {
                    hS = fmaf((m < 2) ? dth : dt, kH, hB);
                } else {
                    hB = fmaf(dt6, accH, hB);
                    hS = hB;
                }
                s_h16[(buf ^ 1) * 272 + ks * 136 + j] = __float2half_rn(hS);   // earliest publish

                // (i,f) path — off the barrier-critical chain
                const __half2 tif_x = pairsum(red4(aXi), red4(aXf));
                const unsigned e_if = __shfl_xor_sync(0xffffffffu, h2u(tif_x), 16);
                const __half2 tif_o = pairsum(red4(aOi), red4(aOf));   // includes pre
                const __half2 z_if  = __hadd2(tif_o, u2h2(e_if));
                const __half2 s_if  = __hfma2(tanh_h2(z_if), H_HALF, H_HALF); // z pre-scaled

                const __half2 g2 = __high2half2(s_og);            // (g, g)
                const __half2 m2 = __hmul2(s_if, g2);             // (i*g, f*g)
                const float ig = __half2float(__low2half(m2));
                const float sf = __half2float(__high2half(s_if));

                const float kC = fmaf(sf, cS, ig - cS);           // dc = i*g + (f-1)*c
                if (m == 0) accC = kC;
                else if (m == 3) accC += kC;
                else accC = fmaf(2.0f, kC, accC);
                if (m < 3) {
                    cS = fmaf((m < 2) ? dth : dt, kC, cB);
                } else {
                    cB = fmaf(dt6, accC, cB);
                    cS = cB;
                }

                // last eval of the timestep also publishes next x (rides the same barrier)
                if (sub == 3 && m == 3 && t < 2 * FF)
                    s_x[(xb ^ 1) * 128 + t] = xr;

                buf ^= 1;
                __syncthreads();
                // post-barrier: tanh(c) for next eval hides under the next MAC issue
                tcs = tanh_ex(cS);
            }
        }
        dtc = dtn;
        out[(size_t)batch * SS * HH + (size_t)sidx * HH + j] = hB;
    }
}

extern "C" void kernel_launch(void* const* d_in, const int* in_sizes, int n_in,
                              void* d_out, int out_size) {
    const float* x  = (const float*)d_in[0];
    const float* td = (const float*)d_in[1];
    const float* Wi = (const float*)d_in[2];
    const float* bi = (const float*)d_in[3];
    const float* Wf = (const float*)d_in[4];
    const float* bf = (const float*)d_in[5];
    const float* Wo = (const float*)d_in[6];
    const float* bo = (const float*)d_in[7];
    const float* Wg = (const float*)d_in[8];
    const float* bg = (const float*)d_in[9];
    float* out = (float*)d_out;

    cudaFuncSetAttribute(clstm_kernel, cudaFuncAttributeMaxDynamicSharedMemorySize, SMEM_BYTES);

    pack_kernel<<<64, NT>>>(Wi, bi, Wf, bf, Wo, bo, Wg, bg);
    clstm_kernel<<<BB / 2, NT, SMEM_BYTES>>>(x, td, out);
}

// round 11
// speedup vs baseline: 1.2787x; 1.0648x over previous
#include <cuda_runtime.h>
#include <cuda_fp16.h>

#define BB 256
#define SS 512
#define FF 64
#define HH 128
#define NT 256

// Weights packed along k: g_wk[gate][kp][j] = half2(W[FF+2kp][j], W[FF+2kp+1][j])
// Gates i,f,o are PRE-SCALED by 0.5 (exact) so sigmoid args need no runtime mul.
__device__ __align__(16) __half2 g_wk[4 * 64 * 128];
__device__ __align__(16) float4  g_xw4[64 * 128];    // (xk,j) -> (.5wi,.5wf,.5wo,wg)
__device__ __align__(16) float4  g_bias4[128];

__global__ void pack_kernel(const float* __restrict__ Wi, const float* __restrict__ bi,
                            const float* __restrict__ Wf, const float* __restrict__ bf,
                            const float* __restrict__ Wo, const float* __restrict__ bo,
                            const float* __restrict__ Wg, const float* __restrict__ bg) {
    const int kp = blockIdx.x;       // 0..63 (k-pair)
    const int t  = threadIdx.x;
    const int j  = t & 127;
    const int pr = t >> 7;
    const int d0 = FF + 2 * kp, d1 = FF + 2 * kp + 1;
    if (pr == 0) {
        g_wk[0 * 8192 + kp * 128 + j] = __floats2half2_rn(0.5f * Wi[d0 * HH + j], 0.5f * Wi[d1 * HH + j]);
        g_wk[1 * 8192 + kp * 128 + j] = __floats2half2_rn(0.5f * Wf[d0 * HH + j], 0.5f * Wf[d1 * HH + j]);
        g_xw4[kp * 128 + j] = make_float4(0.5f * Wi[kp * HH + j], 0.5f * Wf[kp * HH + j],
                                          0.5f * Wo[kp * HH + j], Wg[kp * HH + j]);
    } else {
        g_wk[2 * 8192 + kp * 128 + j] = __floats2half2_rn(0.5f * Wo[d0 * HH + j], 0.5f * Wo[d1 * HH + j]);
        g_wk[3 * 8192 + kp * 128 + j] = __floats2half2_rn(Wg[d0 * HH + j], Wg[d1 * HH + j]);
        if (kp == 0) g_bias4[j] = make_float4(0.5f * bi[j], 0.5f * bf[j], 0.5f * bo[j], bg[j]);
    }
}

__device__ __forceinline__ float fast_ex2(float a) { float r; asm("ex2.approx.f32 %0, %1;" : "=f"(r) : "f"(a)); return r; }
__device__ __forceinline__ float fast_rcp(float a) { float r; asm("rcp.approx.f32 %0, %1;" : "=f"(r) : "f"(a)); return r; }
__device__ __forceinline__ float tanh_ex(float x) { return fmaf(-2.0f, fast_rcp(1.0f + fast_ex2(2.8853900817779268f * x)), 1.0f); }

__device__ __forceinline__ __half2 u2h2(unsigned u) { __half2 r; *reinterpret_cast<unsigned*>(&r) = u; return r; }
__device__ __forceinline__ unsigned h2u(__half2 h) { return *reinterpret_cast<unsigned*>(&h); }
__device__ __forceinline__ __half2 tanh_h2(__half2 a) {
    unsigned r, x = h2u(a);
    asm("tanh.approx.f16x2 %0, %1;" : "=r"(r) : "r"(x));
    return u2h2(r);
}
__device__ __forceinline__ __half2 pairsum(__half2 a, __half2 b) {
    const unsigned lo = __byte_perm(h2u(a), h2u(b), 0x5410);
    const unsigned hi = __byte_perm(h2u(a), h2u(b), 0x7632);
    return __hadd2(u2h2(lo), u2h2(hi));
}
__device__ __forceinline__ __half2 red2(const __half2* a) { return __hadd2(a[0], a[1]); }

// Smem: [0,131072) float4 s_xw | [131072,+1088) half s_h16[2 buf] | [132160,+1024) float s_x[2][128]
#define SMH_OFF 131072
#define SX_OFF  132160
#define SMEM_BYTES (132160 + 1024)

__global__ void __launch_bounds__(NT, 1)
clstm_kernel(const float* __restrict__ x, const float* __restrict__ td, float* __restrict__ out) {
    extern __shared__ char sm[];
    float4* s_xw  = reinterpret_cast<float4*>(sm);
    __half* s_h16 = reinterpret_cast<__half*>(sm + SMH_OFF);
    float*  s_x   = reinterpret_cast<float*>(sm + SX_OFF);   // [2][128]

    const int t    = threadIdx.x;
    const int lane = t & 31;
    const int j    = ((t >> 5) << 4) | (lane & 15);
    const int ks   = (lane >> 4) & 1;          // k-half AND batch owner
    const int b0   = blockIdx.x * 2;
    const int batch = b0 + ks;

    // Weights: 4 gates x 32 k-pairs (own k-half). 128 regs, shared across both batches.
    __half2 wi[32], wf[32], wo[32], wg[32];
#pragma unroll
    for (int q = 0; q < 32; q++) {
        const int kp = ks * 32 + q;
        wi[q] = g_wk[0 * 8192 + kp * 128 + j];
        wf[q] = g_wk[1 * 8192 + kp * 128 + j];
        wo[q] = g_wk[2 * 8192 + kp * 128 + j];
        wg[q] = g_wk[3 * 8192 + kp * 128 + j];
    }
#pragma unroll 4
    for (int i = t; i < FF * 128; i += NT) s_xw[i] = g_xw4[i];
    const float4 bias4 = g_bias4[j];
    const float biasA[4] = {bias4.x, bias4.y, bias4.z, bias4.w};

    const __half2 H_HALF = __floats2half2_rn(0.5f, 0.5f);
    const __half2 H_SM   = __floats2half2_rn(0.5f, 1.0f);
    const __half2 H_SB   = __floats2half2_rn(0.5f, 0.0f);

    float hB = 0.f, cB = 0.f, hS = 0.f, cS = 0.f, tcs = 0.f;
    int buf = 0;
    s_h16[t] = __float2half_rn(0.f);
    if (t < 16) s_h16[256 + t] = __float2half_rn(0.f);

    // prologue prefetch: x[0] into s_x[0], dt for sidx 0 into regs
    if (t < 2 * FF)
        s_x[t] = x[(size_t)(b0 + (t >> 6)) * SS * FF + (t & 63)];
    float dtc = fminf(__ldg(&td[(size_t)batch * SS]), 1.0f) * 0.25f;
    __syncthreads();

#pragma unroll 1
    for (int sidx = 0; sidx < SS; sidx++) {
        const int xb = sidx & 1;
        const float dt  = dtc;
        const float dth = 0.5f * dt, dt6 = dt * (1.0f / 6.0f);

        // prefetch next timestep's x / dt (consumed next iteration; hidden by 16 evals)
        const int nidx = (sidx + 1 < SS) ? sidx + 1 : sidx;
        float xr = 0.f;
        if (t < 2 * FF)
            xr = x[(size_t)(b0 + (t >> 6)) * SS * FF + (size_t)nidx * FF + (t & 63)];
        const float dtn = fminf(__ldg(&td[(size_t)batch * SS + nidx]), 1.0f) * 0.25f;

        // pre = bias + x_t @ W_x (fp32, hoisted over all 16 evals); gates i,f,o pre-scaled
        float xpa[4] = {0.f, 0.f, 0.f, 0.f}, xpb[4] = {0.f, 0.f, 0.f, 0.f};
#pragma unroll 8
        for (int q = 0; q < 32; q++) {
            const int kk = ks * 32 + q;
            const float4 wv = s_xw[kk * 128 + j];
            const float x0 = s_x[xb * 128 + kk], x1 = s_x[xb * 128 + 64 + kk];
            xpa[0] = fmaf(x0, wv.x, xpa[0]); xpa[1] = fmaf(x0, wv.y, xpa[1]);
            xpa[2] = fmaf(x0, wv.z, xpa[2]); xpa[3] = fmaf(x0, wv.w, xpa[3]);
            xpb[0] = fmaf(x1, wv.x, xpb[0]); xpb[1] = fmaf(x1, wv.y, xpb[1]);
            xpb[2] = fmaf(x1, wv.z, xpb[2]); xpb[3] = fmaf(x1, wv.w, xpb[3]);
        }
        float pre[4];
#pragma unroll
        for (int g = 0; g < 4; g++) {
            const float mine = ks ? xpb[g] : xpa[g];
            const float oth  = ks ? xpa[g] : xpb[g];
            pre[g] = biasA[g] + mine + __shfl_xor_sync(0xffffffffu, oth, 16);
        }
        // pre injected as chain-0 initializer of each own-batch gate stream: (pre, 0) in fp16
        const __half2 ini_i = __floats2half2_rn(pre[0], 0.f);
        const __half2 ini_f = __floats2half2_rn(pre[1], 0.f);
        const __half2 ini_o = __floats2half2_rn(pre[2], 0.f);
        const __half2 ini_g = __floats2half2_rn(pre[3], 0.f);

#pragma unroll 1
        for (int sub = 0; sub < 4; sub++) {
            float accH = 0.f, accC = 0.f;
#pragma unroll
            for (int m = 0; m < 4; m++) {
                const __half* hb = s_h16 + buf * 272;
                const uint4* hpo = reinterpret_cast<const uint4*>(hb) + 25 * ks;        // own batch
                const uint4* hpx = reinterpret_cast<const uint4*>(hb) + (17 - 9 * ks);  // other batch

                // ---- MAC: 256 HFMA2, 16 LDS.128 (broadcast), prefetch distance 2 ----
                // 2 fp16 chains per stream (ch = q&1), 16 HFMA2 per chain.
                uint4 ho[8], hx[8];
                ho[0] = hpo[0]; hx[0] = hpx[0];
                ho[1] = hpo[1]; hx[1] = hpx[1];
                __half2 aOi[2], aOf[2], aOo[2], aOg[2];
                __half2 aXi[2], aXf[2], aXo[2], aXg[2];
#pragma unroll
                for (int r = 0; r < 8; r++) {
                    if (r < 6) { ho[r + 2] = hpo[r + 2]; hx[r + 2] = hpx[r + 2]; }
                    const uint4 co = ho[r], cx = hx[r];
                    const __half2 e0[4] = {u2h2(co.x), u2h2(co.y), u2h2(co.z), u2h2(co.w)};
                    const __half2 e1[4] = {u2h2(cx.x), u2h2(cx.y), u2h2(cx.z), u2h2(cx.w)};
#pragma unroll
                    for (int q = 0; q < 4; q++) {
                        const int kp = r * 4 + q;
                        const int ch = q & 1;
                        if (r == 0 && q < 2) {
                            if (q == 0) {   // chain 0 carries pre (free injection)
                                aOi[0] = __hfma2(e0[q], wi[kp], ini_i);
                                aOf[0] = __hfma2(e0[q], wf[kp], ini_f);
                                aOo[0] = __hfma2(e0[q], wo[kp], ini_o);
                                aOg[0] = __hfma2(e0[q], wg[kp], ini_g);
                            } else {
                                aOi[1] = __hmul2(e0[q], wi[kp]);
                                aOf[1] = __hmul2(e0[q], wf[kp]);
                                aOo[1] = __hmul2(e0[q], wo[kp]);
                                aOg[1] = __hmul2(e0[q], wg[kp]);
                            }
                            aXi[ch] = __hmul2(e1[q], wi[kp]);
                            aXf[ch] = __hmul2(e1[q], wf[kp]);
                            aXo[ch] = __hmul2(e1[q], wo[kp]);
                            aXg[ch] = __hmul2(e1[q], wg[kp]);
                        } else {
                            aOi[ch] = __hfma2(e0[q], wi[kp], aOi[ch]);
                            aOf[ch] = __hfma2(e0[q], wf[kp], aOf[ch]);
                            aOo[ch] = __hfma2(e0[q], wo[kp], aOo[ch]);
                            aOg[ch] = __hfma2(e0[q], wg[kp], aOg[ch]);
                            aXi[ch] = __hfma2(e1[q], wi[kp], aXi[ch]);
                            aXf[ch] = __hfma2(e1[q], wf[kp], aXf[ch]);
                            aXo[ch] = __hfma2(e1[q], wo[kp], aXo[ch]);
                            aXg[ch] = __hfma2(e1[q], wg[kp], aXg[ch]);
                        }
                    }
                }
                // (o,g) path FIRST — h-publish chain is barrier-critical
                const __half2 tog_x = pairsum(red2(aXo), red2(aXg));
                const unsigned e_og = __shfl_xor_sync(0xffffffffu, h2u(tog_x), 16);
                const __half2 tog_o = pairsum(red2(aOo), red2(aOg));   // includes pre
                const __half2 z_og  = __hadd2(tog_o, u2h2(e_og));
                const __half2 s_og  = __hfma2(tanh_h2(z_og), H_SM, H_SB);  // z pre-scaled

                const float so = __half2float(__low2half(s_og));
                const float kH = fmaf(so, tcs, -hS);              // dh = o*tanh(c) - h
                if (m == 0) accH = kH;
                else if (m == 3) accH += kH;
                else accH = fmaf(2.0f, kH, accH);
                if (m < 3) {
                    hS = fmaf((m < 2) ? dth : dt, kH, hB);
                } else {
                    hB = fmaf(dt6, accH, hB);
                    hS = hB;
                }
                s_h16[(buf ^ 1) * 272 + ks * 136 + j] = __float2half_rn(hS);   // earliest publish

                // (i,f) path — off the barrier-critical chain
                const __half2 tif_x = pairsum(red2(aXi), red2(aXf));
                const unsigned e_if = __shfl_xor_sync(0xffffffffu, h2u(tif_x), 16);
                const __half2 tif_o = pairsum(red2(aOi), red2(aOf));   // includes pre
                const __half2 z_if  = __hadd2(tif_o, u2h2(e_if));
                const __half2 s_if  = __hfma2(tanh_h2(z_if), H_HALF, H_HALF); // z pre-scaled

                const __half2 g2 = __high2half2(s_og);            // (g, g)
                const __half2 m2 = __hmul2(s_if, g2);             // (i*g, f*g)
                const float ig = __half2float(__low2half(m2));
                const float sf = __half2float(__high2half(s_if));

                const float kC = fmaf(sf, cS, ig - cS);           // dc = i*g + (f-1)*c
                if (m == 0) accC = kC;
                else if (m == 3) accC += kC;
                else accC = fmaf(2.0f, kC, accC);
                if (m < 3) {
                    cS = fmaf((m < 2) ? dth : dt, kC, cB);
                } else {
                    cB = fmaf(dt6, accC, cB);
                    cS = cB;
                }

                // last eval of the timestep also publishes next x (rides the same barrier)
                if (sub == 3 && m == 3 && t < 2 * FF)
                    s_x[(xb ^ 1) * 128 + t] = xr;

                buf ^= 1;
                __syncthreads();
                // post-barrier: tanh(c) for next eval hides under the next MAC issue
                tcs = tanh_ex(cS);
            }
        }
        dtc = dtn;
        out[(size_t)batch * SS * HH + (size_t)sidx * HH + j] = hB;
    }
}

extern "C" void kernel_launch(void* const* d_in, const int* in_sizes, int n_in,
                              void* d_out, int out_size) {
    const float* x  = (const float*)d_in[0];
    const float* td = (const float*)d_in[1];
    const float* Wi = (const float*)d_in[2];
    const float* bi = (const float*)d_in[3];
    const float* Wf = (const float*)d_in[4];
    const float* bf = (const float*)d_in[5];
    const float* Wo = (const float*)d_in[6];
    const float* bo = (const float*)d_in[7];
    const float* Wg = (const float*)d_in[8];
    const float* bg = (const float*)d_in[9];
    float* out = (float*)d_out;

    cudaFuncSetAttribute(clstm_kernel, cudaFuncAttributeMaxDynamicSharedMemorySize, SMEM_BYTES);

    pack_kernel<<<64, NT>>>(Wi, bi, Wf, bf, Wo, bo, Wg, bg);
    clstm_kernel<<<BB / 2, NT, SMEM_BYTES>>>(x, td, out);
}

// round 12
// speedup vs baseline: 1.3021x; 1.0183x over previous
#include <cuda_runtime.h>
#include <cuda_fp16.h>

#define BB 256
#define SS 512
#define FF 64
#define HH 128
#define NT 256

// Weights packed along k: g_wk[gate][kp][j] = half2(W[FF+2kp][j], W[FF+2kp+1][j])
// Gates i,f,o are PRE-SCALED by 0.5 (exact) so sigmoid args need no runtime mul.
__device__ __align__(16) __half2 g_wk[4 * 64 * 128];
__device__ __align__(16) float4  g_xw4[64 * 128];    // (xk,j) -> (.5wi,.5wf,.5wo,wg)
__device__ __align__(16) float4  g_bias4[128];

__global__ void pack_kernel(const float* __restrict__ Wi, const float* __restrict__ bi,
                            const float* __restrict__ Wf, const float* __restrict__ bf,
                            const float* __restrict__ Wo, const float* __restrict__ bo,
                            const float* __restrict__ Wg, const float* __restrict__ bg) {
    const int kp = blockIdx.x;       // 0..63 (k-pair)
    const int t  = threadIdx.x;
    const int j  = t & 127;
    const int pr = t >> 7;
    const int d0 = FF + 2 * kp, d1 = FF + 2 * kp + 1;
    if (pr == 0) {
        g_wk[0 * 8192 + kp * 128 + j] = __floats2half2_rn(0.5f * Wi[d0 * HH + j], 0.5f * Wi[d1 * HH + j]);
        g_wk[1 * 8192 + kp * 128 + j] = __floats2half2_rn(0.5f * Wf[d0 * HH + j], 0.5f * Wf[d1 * HH + j]);
        g_xw4[kp * 128 + j] = make_float4(0.5f * Wi[kp * HH + j], 0.5f * Wf[kp * HH + j],
                                          0.5f * Wo[kp * HH + j], Wg[kp * HH + j]);
    } else {
        g_wk[2 * 8192 + kp * 128 + j] = __floats2half2_rn(0.5f * Wo[d0 * HH + j], 0.5f * Wo[d1 * HH + j]);
        g_wk[3 * 8192 + kp * 128 + j] = __floats2half2_rn(Wg[d0 * HH + j], Wg[d1 * HH + j]);
        if (kp == 0) g_bias4[j] = make_float4(0.5f * bi[j], 0.5f * bf[j], 0.5f * bo[j], bg[j]);
    }
}

__device__ __forceinline__ float fast_ex2(float a) { float r; asm("ex2.approx.f32 %0, %1;" : "=f"(r) : "f"(a)); return r; }
__device__ __forceinline__ float fast_rcp(float a) { float r; asm("rcp.approx.f32 %0, %1;" : "=f"(r) : "f"(a)); return r; }
__device__ __forceinline__ float tanh_ex(float x) { return fmaf(-2.0f, fast_rcp(1.0f + fast_ex2(2.8853900817779268f * x)), 1.0f); }

__device__ __forceinline__ __half2 u2h2(unsigned u) { __half2 r; *reinterpret_cast<unsigned*>(&r) = u; return r; }
__device__ __forceinline__ unsigned h2u(__half2 h) { return *reinterpret_cast<unsigned*>(&h); }
__device__ __forceinline__ __half2 tanh_h2(__half2 a) {
    unsigned r, x = h2u(a);
    asm("tanh.approx.f16x2 %0, %1;" : "=r"(r) : "r"(x));
    return u2h2(r);
}
// half2(lo a + hi a, lo b + hi b): 2 PRMT (alu pipe) + 1 HADD2
__device__ __forceinline__ __half2 pairsum(__half2 a, __half2 b) {
    const unsigned lo = __byte_perm(h2u(a), h2u(b), 0x5410);
    const unsigned hi = __byte_perm(h2u(a), h2u(b), 0x7632);
    return __hadd2(u2h2(lo), u2h2(hi));
}

// Smem: [0,131072) float4 s_xw | [131072,+1088) half s_h16[2 buf] | [132160,+1024) float s_x[2][128]
#define SMH_OFF 131072
#define SX_OFF  132160
#define SMEM_BYTES (132160 + 1024)

__global__ void __launch_bounds__(NT, 1)
clstm_kernel(const float* __restrict__ x, const float* __restrict__ td, float* __restrict__ out) {
    extern __shared__ char sm[];
    float4* s_xw  = reinterpret_cast<float4*>(sm);
    __half* s_h16 = reinterpret_cast<__half*>(sm + SMH_OFF);
    float*  s_x   = reinterpret_cast<float*>(sm + SX_OFF);   // [2][128]

    const int t    = threadIdx.x;
    const int lane = t & 31;
    const int j    = ((t >> 5) << 4) | (lane & 15);
    const int ks   = (lane >> 4) & 1;          // k-half AND batch owner
    const int b0   = blockIdx.x * 2;
    const int batch = b0 + ks;

    // Weights: 4 gates x 32 k-pairs (own k-half). 128 regs, shared across both batches.
    __half2 wi[32], wf[32], wo[32], wg[32];
#pragma unroll
    for (int q = 0; q < 32; q++) {
        const int kp = ks * 32 + q;
        wi[q] = g_wk[0 * 8192 + kp * 128 + j];
        wf[q] = g_wk[1 * 8192 + kp * 128 + j];
        wo[q] = g_wk[2 * 8192 + kp * 128 + j];
        wg[q] = g_wk[3 * 8192 + kp * 128 + j];
    }
#pragma unroll 4
    for (int i = t; i < FF * 128; i += NT) s_xw[i] = g_xw4[i];
    const float4 bias4 = g_bias4[j];
    const float biasA[4] = {bias4.x, bias4.y, bias4.z, bias4.w};

    const __half2 H_HALF = __floats2half2_rn(0.5f, 0.5f);
    const __half2 H_SM   = __floats2half2_rn(0.5f, 1.0f);
    const __half2 H_SB   = __floats2half2_rn(0.5f, 0.0f);

    float hB = 0.f, cB = 0.f, hS = 0.f, cS = 0.f, tcs = 0.f;
    int buf = 0;
    s_h16[t] = __float2half_rn(0.f);
    if (t < 16) s_h16[256 + t] = __float2half_rn(0.f);

    // prologue prefetch: x[0] into s_x[0], dt for sidx 0 into regs
    if (t < 2 * FF)
        s_x[t] = x[(size_t)(b0 + (t >> 6)) * SS * FF + (t & 63)];
    float dtc = fminf(__ldg(&td[(size_t)batch * SS]), 1.0f) * 0.25f;
    __syncthreads();

#pragma unroll 1
    for (int sidx = 0; sidx < SS; sidx++) {
        const int xb = sidx & 1;
        const float dt  = dtc;
        const float dth = 0.5f * dt, dt6 = dt * (1.0f / 6.0f);

        // prefetch next timestep's x / dt (consumed next iteration; hidden by 16 evals)
        const int nidx = (sidx + 1 < SS) ? sidx + 1 : sidx;
        float xr = 0.f;
        if (t < 2 * FF)
            xr = x[(size_t)(b0 + (t >> 6)) * SS * FF + (size_t)nidx * FF + (t & 63)];
        const float dtn = fminf(__ldg(&td[(size_t)batch * SS + nidx]), 1.0f) * 0.25f;

        // pre = bias + x_t @ W_x (fp32, hoisted over all 16 evals); gates i,f,o pre-scaled
        float xpa[4] = {0.f, 0.f, 0.f, 0.f}, xpb[4] = {0.f, 0.f, 0.f, 0.f};
#pragma unroll 8
        for (int q = 0; q < 32; q++) {
            const int kk = ks * 32 + q;
            const float4 wv = s_xw[kk * 128 + j];
            const float x0 = s_x[xb * 128 + kk], x1 = s_x[xb * 128 + 64 + kk];
            xpa[0] = fmaf(x0, wv.x, xpa[0]); xpa[1] = fmaf(x0, wv.y, xpa[1]);
            xpa[2] = fmaf(x0, wv.z, xpa[2]); xpa[3] = fmaf(x0, wv.w, xpa[3]);
            xpb[0] = fmaf(x1, wv.x, xpb[0]); xpb[1] = fmaf(x1, wv.y, xpb[1]);
            xpb[2] = fmaf(x1, wv.z, xpb[2]); xpb[3] = fmaf(x1, wv.w, xpb[3]);
        }
        float pre[4];
#pragma unroll
        for (int g = 0; g < 4; g++) {
            const float mine = ks ? xpb[g] : xpa[g];
            const float oth  = ks ? xpa[g] : xpb[g];
            pre[g] = biasA[g] + mine + __shfl_xor_sync(0xffffffffu, oth, 16);
        }
        // pre injected as chain initializer of each own-batch gate stream: (pre, 0) in fp16
        const __half2 ini_i = __floats2half2_rn(pre[0], 0.f);
        const __half2 ini_f = __floats2half2_rn(pre[1], 0.f);
        const __half2 ini_o = __floats2half2_rn(pre[2], 0.f);
        const __half2 ini_g = __floats2half2_rn(pre[3], 0.f);

#pragma unroll 1
        for (int sub = 0; sub < 4; sub++) {
            float accH = 0.f, accC = 0.f;
#pragma unroll
            for (int m = 0; m < 4; m++) {
                const __half* hb = s_h16 + buf * 272;
                const uint4* hpo = reinterpret_cast<const uint4*>(hb) + 25 * ks;        // own batch
                const uint4* hpx = reinterpret_cast<const uint4*>(hb) + (17 - 9 * ks);  // other batch

                // ---- MAC: 256 HFMA2, 16 LDS.128 (broadcast), prefetch distance 2 ----
                // ONE fp16 chain per stream (32 HFMA2 each); no per-stream reduction.
                uint4 ho[8], hx[8];
                ho[0] = hpo[0]; hx[0] = hpx[0];
                ho[1] = hpo[1]; hx[1] = hpx[1];
                __half2 aOi, aOf, aOo, aOg, aXi, aXf, aXo, aXg;
#pragma unroll
                for (int r = 0; r < 8; r++) {
                    if (r < 6) { ho[r + 2] = hpo[r + 2]; hx[r + 2] = hpx[r + 2]; }
                    const uint4 co = ho[r], cx = hx[r];
                    const __half2 e0[4] = {u2h2(co.x), u2h2(co.y), u2h2(co.z), u2h2(co.w)};
                    const __half2 e1[4] = {u2h2(cx.x), u2h2(cx.y), u2h2(cx.z), u2h2(cx.w)};
#pragma unroll
                    for (int q = 0; q < 4; q++) {
                        const int kp = r * 4 + q;
                        if (r == 0 && q == 0) {
                            aOi = __hfma2(e0[q], wi[kp], ini_i);   // chain carries pre (free)
                            aOf = __hfma2(e0[q], wf[kp], ini_f);
                            aOo = __hfma2(e0[q], wo[kp], ini_o);
                            aOg = __hfma2(e0[q], wg[kp], ini_g);
                            aXi = __hmul2(e1[q], wi[kp]);
                            aXf = __hmul2(e1[q], wf[kp]);
                            aXo = __hmul2(e1[q], wo[kp]);
                            aXg = __hmul2(e1[q], wg[kp]);
                        } else {
                            aOi = __hfma2(e0[q], wi[kp], aOi);
                            aOf = __hfma2(e0[q], wf[kp], aOf);
                            aOo = __hfma2(e0[q], wo[kp], aOo);
                            aOg = __hfma2(e0[q], wg[kp], aOg);
                            aXi = __hfma2(e1[q], wi[kp], aXi);
                            aXf = __hfma2(e1[q], wf[kp], aXf);
                            aXo = __hfma2(e1[q], wo[kp], aXo);
                            aXg = __hfma2(e1[q], wg[kp], aXg);
                        }
                    }
                }
                // (o,g) path FIRST — h-publish chain is barrier-critical
                const __half2 tog_x = pairsum(aXo, aXg);
                const unsigned e_og = __shfl_xor_sync(0xffffffffu, h2u(tog_x), 16);
                const __half2 tog_o = pairsum(aOo, aOg);           // includes pre
                const __half2 z_og  = __hadd2(tog_o, u2h2(e_og));
                const __half2 s_og  = __hfma2(tanh_h2(z_og), H_SM, H_SB);  // z pre-scaled

                const float so = __half2float(__low2half(s_og));
                const float kH = fmaf(so, tcs, -hS);              // dh = o*tanh(c) - h
                if (m == 0) accH = kH;
                else if (m == 3) accH += kH;
                else accH = fmaf(2.0f, kH, accH);
                if (m < 3) {
                    hS = fmaf((m < 2) ? dth : dt, kH, hB);
                } else {
                    hB = fmaf(dt6, accH, hB);
                    hS = hB;
                }
                s_h16[(buf ^ 1) * 272 + ks * 136 + j] = __float2half_rn(hS);   // earliest publish

                // (i,f) path — off the barrier-critical chain
                const __half2 tif_x = pairsum(aXi, aXf);
                const unsigned e_if = __shfl_xor_sync(0xffffffffu, h2u(tif_x), 16);
                const __half2 tif_o = pairsum(aOi, aOf);           // includes pre
                const __half2 z_if  = __hadd2(tif_o, u2h2(e_if));
                const __half2 s_if  = __hfma2(tanh_h2(z_if), H_HALF, H_HALF); // z pre-scaled

                const __half2 g2 = __high2half2(s_og);            // (g, g)
                const __half2 m2 = __hmul2(s_if, g2);             // (i*g, f*g)
                const float ig = __half2float(__low2half(m2));
                const float sf = __half2float(__high2half(s_if));

                const float kC = fmaf(sf, cS, ig - cS);           // dc = i*g + (f-1)*c
                if (m == 0) accC = kC;
                else if (m == 3) accC += kC;
                else accC = fmaf(2.0f, kC, accC);
                if (m < 3) {
                    cS = fmaf((m < 2) ? dth : dt, kC, cB);
                } else {
                    cB = fmaf(dt6, accC, cB);
                    cS = cB;
                }

                // last eval of the timestep also publishes next x (rides the same barrier)
                if (sub == 3 && m == 3 && t < 2 * FF)
                    s_x[(xb ^ 1) * 128 + t] = xr;

                buf ^= 1;
                __syncthreads();
                // post-barrier: tanh(c) for next eval hides under the next MAC issue
                tcs = tanh_ex(cS);
            }
        }
        dtc = dtn;
        out[(size_t)batch * SS * HH + (size_t)sidx * HH + j] = hB;
    }
}

extern "C" void kernel_launch(void* const* d_in, const int* in_sizes, int n_in,
                              void* d_out, int out_size) {
    const float* x  = (const float*)d_in[0];
    const float* td = (const float*)d_in[1];
    const float* Wi = (const float*)d_in[2];
    const float* bi = (const float*)d_in[3];
    const float* Wf = (const float*)d_in[4];
    const float* bf = (const float*)d_in[5];
    const float* Wo = (const float*)d_in[6];
    const float* bo = (const float*)d_in[7];
    const float* Wg = (const float*)d_in[8];
    const float* bg = (const float*)d_in[9];
    float* out = (float*)d_out;

    cudaFuncSetAttribute(clstm_kernel, cudaFuncAttributeMaxDynamicSharedMemorySize, SMEM_BYTES);

    pack_kernel<<<64, NT>>>(Wi, bi, Wf, bf, Wo, bo, Wg, bg);
    clstm_kernel<<<BB / 2, NT, SMEM_BYTES>>>(x, td, out);
}